// round 1
// baseline (speedup 1.0000x reference)
#include <cuda_runtime.h>
#include <math.h>

#define CC    128          // channels
#define HHID  512          // expert hidden dim
#define EE    8            // routed experts
#define BB    8            // batch
#define HHW   9216         // 96*96
#define NTOK  73728        // BB*HHW
#define TT    64           // tokens per tile
#define XS_LD 68           // padded lead dim for x/h tiles [k][t]
#define WS_LD 132          // padded lead dim for w tiles  [k][c]
#define NOUT  (NTOK*CC)    // 9437184

#define SMEM_FLOATS (2*128*XS_LD + 128*WS_LD)
#define SMEM_BYTES  (SMEM_FLOATS*4 + TT*8)

// scratch (static device globals; no allocation in kernel_launch)
__device__ float g_xT[(size_t)NTOK*CC];     // token-major x
__device__ int   g_tok[EE*NTOK];
__device__ float g_wt[EE*NTOK];
__device__ int   g_cnt[EE];
__device__ float g_probsum[EE];
__device__ int   g_loadsum[EE];

__device__ __forceinline__ float gelu_exact(float v) {
    return 0.5f * v * (1.0f + erff(v * 0.70710678118654752440f));
}

// ---------------------------------------------------------------- init: out = x, zero accum
__global__ void init_kernel(const float* __restrict__ x, float* __restrict__ out) {
    int i = blockIdx.x * blockDim.x + threadIdx.x;   // NOUT/4 threads exactly
    ((float4*)out)[i] = ((const float4*)x)[i];
    if (blockIdx.x == 0 && threadIdx.x < EE) {
        g_cnt[threadIdx.x] = 0;
        g_probsum[threadIdx.x] = 0.f;
        g_loadsum[threadIdx.x] = 0;
    }
}

// ---------------------------------------------------------------- transpose x [B,C,HW] -> xT [N,C]
__global__ void transpose_kernel(const float* __restrict__ x) {
    __shared__ float t[32][33];
    int b = blockIdx.z, c0 = blockIdx.y * 32, s0 = blockIdx.x * 32;
    int tx = threadIdx.x, ty = threadIdx.y;
    #pragma unroll
    for (int i = 0; i < 4; i++) {
        int c = c0 + ty + i * 8;
        t[ty + i * 8][tx] = x[(size_t)(b * CC + c) * HHW + s0 + tx];
    }
    __syncthreads();
    #pragma unroll
    for (int i = 0; i < 4; i++) {
        int s = s0 + ty + i * 8;
        g_xT[(size_t)(b * HHW + s) * CC + c0 + tx] = t[tx][ty + i * 8];
    }
}

// ---------------------------------------------------------------- router: softmax, top-3, lists, aux stats
__global__ void router_kernel(const float* __restrict__ x,
                              const float* __restrict__ gw,
                              const float* __restrict__ gb) {
    __shared__ float gws[EE * CC];
    __shared__ int   scnt[EE];
    __shared__ float sprob[EE];
    __shared__ int   sbase[EE];
    int tid = threadIdx.x;
    for (int i = tid; i < EE * CC; i += blockDim.x) gws[i] = gw[i];
    if (tid < EE) { scnt[tid] = 0; sprob[tid] = 0.f; }
    __syncthreads();

    int n = blockIdx.x * 256 + tid;                  // NTOK/256 blocks exactly
    int b = n / HHW, s = n - b * HHW;
    const float* xb = x + (size_t)b * CC * HHW + s;

    float acc[EE];
    #pragma unroll
    for (int e = 0; e < EE; e++) acc[e] = gb[e];
    for (int c = 0; c < CC; c++) {
        float xv = xb[(size_t)c * HHW];
        #pragma unroll
        for (int e = 0; e < EE; e++) acc[e] += xv * gws[e * CC + c];
    }
    // softmax
    float m = acc[0];
    #pragma unroll
    for (int e = 1; e < EE; e++) m = fmaxf(m, acc[e]);
    float sum = 0.f;
    #pragma unroll
    for (int e = 0; e < EE; e++) { acc[e] = expf(acc[e] - m); sum += acc[e]; }
    float inv = 1.f / sum;
    #pragma unroll
    for (int e = 0; e < EE; e++) { acc[e] *= inv; atomicAdd(&sprob[e], acc[e]); }

    // top-3 (ties -> lowest index, matches lax.top_k)
    float tmp[EE];
    #pragma unroll
    for (int e = 0; e < EE; e++) tmp[e] = acc[e];
    int id[3]; float pv[3]; float wsum = 0.f;
    #pragma unroll
    for (int k = 0; k < 3; k++) {
        int bi = 0; float bv = tmp[0];
        #pragma unroll
        for (int e = 1; e < EE; e++) if (tmp[e] > bv) { bv = tmp[e]; bi = e; }
        id[k] = bi; pv[k] = bv; tmp[bi] = -1.f; wsum += bv;
    }
    int slot[3];
    #pragma unroll
    for (int k = 0; k < 3; k++) slot[k] = atomicAdd(&scnt[id[k]], 1);
    __syncthreads();
    if (tid < EE) {
        sbase[tid] = atomicAdd(&g_cnt[tid], scnt[tid]);
        atomicAdd(&g_probsum[tid], sprob[tid]);
        atomicAdd(&g_loadsum[tid], scnt[tid]);
    }
    __syncthreads();
    float winv = 1.f / wsum;
    #pragma unroll
    for (int k = 0; k < 3; k++) {
        int pos = sbase[id[k]] + slot[k];
        g_tok[id[k] * NTOK + pos] = n;
        g_wt[id[k] * NTOK + pos]  = pv[k] * winv;
    }
}

// ---------------------------------------------------------------- aux loss
__global__ void finalize_kernel(float* __restrict__ out, int out_size) {
    if (threadIdx.x == 0) {
        float a = 0.f;
        for (int e = 0; e < EE; e++) a += g_probsum[e] * (float)g_loadsum[e];
        out[out_size - 1] = (float)EE * a / ((float)NTOK * (float)NTOK);
    }
}

// ---------------------------------------------------------------- fused expert GEMM
// blockIdx.y = expert (0..7 routed, 8 = shared); blockIdx.x = token tile
__global__ __launch_bounds__(256, 1) void moe_gemm_kernel(
    const float* __restrict__ sw1, const float* __restrict__ sb1,
    const float* __restrict__ sw2, const float* __restrict__ sb2,
    const float* __restrict__ ew1, const float* __restrict__ eb1,
    const float* __restrict__ ew2, const float* __restrict__ eb2,
    float* __restrict__ out)
{
    extern __shared__ float sm[];
    float* xs = sm;                       // [128][XS_LD]  x tile (k-major)
    float* hs = sm + 128 * XS_LD;         // [128][XS_LD]  gelu(h) chunk (k-major)
    float* ws = sm + 2 * 128 * XS_LD;     // [128][WS_LD]  weight chunk (k-major)
    int*   tk = (int*)(sm + SMEM_FLOATS);
    float* tw = (float*)(tk + TT);

    int e = blockIdx.y;
    const float *w1, *b1, *w2, *b2;
    int count;
    if (e < EE) {
        count = g_cnt[e];
        w1 = ew1 + (size_t)e * HHID * CC;  b1 = eb1 + e * HHID;
        w2 = ew2 + (size_t)e * CC * HHID;  b2 = eb2 + e * CC;
    } else {
        count = NTOK;
        w1 = sw1; b1 = sb1; w2 = sw2; b2 = sb2;
    }
    int t0g = blockIdx.x * TT;
    if (t0g >= count) return;
    int tid = threadIdx.x;

    if (tid < TT) {
        int idx = t0g + tid;
        if (e < EE) {
            if (idx < count) { tk[tid] = g_tok[e * NTOK + idx]; tw[tid] = g_wt[e * NTOK + idx]; }
            else             { tk[tid] = 0;                     tw[tid] = 0.f; }
        } else { tk[tid] = idx; tw[tid] = 1.f; }
    }
    __syncthreads();

    // gather x rows -> xs[k][t]   (conflict-free smem stores: lanes span t)
    {
        int t   = tid & 63;
        int k4b = tid >> 6;  // 0..3
        const float4* src = (const float4*)(g_xT + (size_t)tk[t] * CC);
        #pragma unroll
        for (int i = 0; i < 8; i++) {
            int k4 = k4b + i * 4;
            float4 v = src[k4];
            xs[(4 * k4 + 0) * XS_LD + t] = v.x;
            xs[(4 * k4 + 1) * XS_LD + t] = v.y;
            xs[(4 * k4 + 2) * XS_LD + t] = v.z;
            xs[(4 * k4 + 3) * XS_LD + t] = v.w;
        }
    }

    int tr0 = (tid >> 5) * 8;       // 8 tokens per thread
    int cc4 = (tid & 31) * 4;       // 4 output columns per thread
    float acc2[8][4];
    #pragma unroll
    for (int i = 0; i < 8; i++)
        #pragma unroll
        for (int c = 0; c < 4; c++) acc2[i][c] = 0.f;

    int hrow  = tid & 127;
    int k4b2  = tid >> 7;           // 0..1

    for (int j = 0; j < 4; j++) {   // hidden-dim chunks of 128
        // stage w1 chunk: ws[k][h] = w1[j*128+h][k]
        {
            const float4* wr = (const float4*)(w1 + (size_t)(j * 128 + hrow) * CC);
            #pragma unroll
            for (int i = 0; i < 16; i++) {
                int k4 = k4b2 + 2 * i;
                float4 v = wr[k4];
                ws[(4 * k4 + 0) * WS_LD + hrow] = v.x;
                ws[(4 * k4 + 1) * WS_LD + hrow] = v.y;
                ws[(4 * k4 + 2) * WS_LD + hrow] = v.z;
                ws[(4 * k4 + 3) * WS_LD + hrow] = v.w;
            }
        }
        __syncthreads();

        // GEMM1: h[t][hid] = x[t][:] . w1[hid][:]
        float acc1[8][4];
        #pragma unroll
        for (int i = 0; i < 8; i++)
            #pragma unroll
            for (int c = 0; c < 4; c++) acc1[i][c] = 0.f;

        #pragma unroll 4
        for (int k = 0; k < 128; k++) {
            float4 b4 = *(const float4*)&ws[k * WS_LD + cc4];
            float4 a0 = *(const float4*)&xs[k * XS_LD + tr0];
            float4 a1 = *(const float4*)&xs[k * XS_LD + tr0 + 4];
            float av[8] = {a0.x, a0.y, a0.z, a0.w, a1.x, a1.y, a1.z, a1.w};
            float bv[4] = {b4.x, b4.y, b4.z, b4.w};
            #pragma unroll
            for (int i = 0; i < 8; i++)
                #pragma unroll
                for (int c = 0; c < 4; c++) acc1[i][c] += av[i] * bv[c];
        }

        // bias + gelu -> hs[k(hid)][t]
        float bi[4];
        #pragma unroll
        for (int c = 0; c < 4; c++) bi[c] = b1[j * 128 + cc4 + c];
        #pragma unroll
        for (int c = 0; c < 4; c++) {
            float4 o0, o1;
            o0.x = gelu_exact(acc1[0][c] + bi[c]);
            o0.y = gelu_exact(acc1[1][c] + bi[c]);
            o0.z = gelu_exact(acc1[2][c] + bi[c]);
            o0.w = gelu_exact(acc1[3][c] + bi[c]);
            o1.x = gelu_exact(acc1[4][c] + bi[c]);
            o1.y = gelu_exact(acc1[5][c] + bi[c]);
            o1.z = gelu_exact(acc1[6][c] + bi[c]);
            o1.w = gelu_exact(acc1[7][c] + bi[c]);
            *(float4*)&hs[(cc4 + c) * XS_LD + tr0]     = o0;
            *(float4*)&hs[(cc4 + c) * XS_LD + tr0 + 4] = o1;
        }
        __syncthreads();

        // stage w2 chunk: ws[k(hid)][c] = w2[c][j*128+k]
        {
            const float* w2r = w2 + (size_t)hrow * HHID + j * 128;
            #pragma unroll
            for (int i = 0; i < 16; i++) {
                int k4 = k4b2 + 2 * i;
                float4 v = *(const float4*)(w2r + 4 * k4);
                ws[(4 * k4 + 0) * WS_LD + hrow] = v.x;
                ws[(4 * k4 + 1) * WS_LD + hrow] = v.y;
                ws[(4 * k4 + 2) * WS_LD + hrow] = v.z;
                ws[(4 * k4 + 3) * WS_LD + hrow] = v.w;
            }
        }
        __syncthreads();

        // GEMM2 accumulate: y[t][c] += h[t][hid] . w2[c][hid]
        #pragma unroll 4
        for (int k = 0; k < 128; k++) {
            float4 b4 = *(const float4*)&ws[k * WS_LD + cc4];
            float4 a0 = *(const float4*)&hs[k * XS_LD + tr0];
            float4 a1 = *(const float4*)&hs[k * XS_LD + tr0 + 4];
            float av[8] = {a0.x, a0.y, a0.z, a0.w, a1.x, a1.y, a1.z, a1.w};
            float bv[4] = {b4.x, b4.y, b4.z, b4.w};
            #pragma unroll
            for (int i = 0; i < 8; i++)
                #pragma unroll
                for (int c = 0; c < 4; c++) acc2[i][c] += av[i] * bv[c];
        }
        __syncthreads();
    }

    // epilogue: weighted atomic accumulate into out [B,C,H,W]
    float b2v[4];
    #pragma unroll
    for (int c = 0; c < 4; c++) b2v[c] = b2[cc4 + c];
    #pragma unroll
    for (int i = 0; i < 8; i++) {
        int t = tr0 + i;
        int n = tk[t];
        float w = tw[t];
        int bb = n / HHW, s = n - bb * HHW;
        float* ob = out + (size_t)(bb * CC) * HHW + s;
        #pragma unroll
        for (int c = 0; c < 4; c++) {
            atomicAdd(&ob[(size_t)(cc4 + c) * HHW], w * (acc2[i][c] + b2v[c]));
        }
    }
}

// ----------------------------------------------------------------
extern "C" void kernel_launch(void* const* d_in, const int* in_sizes, int n_in,
                              void* d_out, int out_size) {
    const float* x   = (const float*)d_in[0];
    const float* sw1 = (const float*)d_in[1];
    const float* sb1 = (const float*)d_in[2];
    const float* sw2 = (const float*)d_in[3];
    const float* sb2 = (const float*)d_in[4];
    const float* gw  = (const float*)d_in[5];
    const float* gb  = (const float*)d_in[6];
    const float* ew1 = (const float*)d_in[7];
    const float* eb1 = (const float*)d_in[8];
    const float* ew2 = (const float*)d_in[9];
    const float* eb2 = (const float*)d_in[10];
    float* out = (float*)d_out;

    cudaFuncSetAttribute(moe_gemm_kernel,
                         cudaFuncAttributeMaxDynamicSharedMemorySize, SMEM_BYTES);

    init_kernel<<<NOUT / 4 / 256, 256>>>(x, out);
    transpose_kernel<<<dim3(HHW / 32, CC / 32, BB), dim3(32, 8)>>>(x);
    router_kernel<<<NTOK / 256, 256>>>(x, gw, gb);
    moe_gemm_kernel<<<dim3(NTOK / TT, EE + 1), 256, SMEM_BYTES>>>(
        sw1, sb1, sw2, sb2, ew1, eb1, ew2, eb2, out);
    finalize_kernel<<<1, 32>>>(out, out_size);
}

// round 3
// speedup vs baseline: 1.9830x; 1.9830x over previous
#include <cuda_runtime.h>
#include <cuda_bf16.h>
#include <math.h>
#include <stdint.h>

#define CC    128          // channels
#define HHID  512          // expert hidden dim
#define EE    8            // routed experts
#define BB    8            // batch
#define HHW   9216         // 96*96
#define NTOK  73728        // BB*HHW
#define NOUT  (NTOK*CC)
#define TMT   128          // tokens per tile (GEMM M)
#define NE1   (EE+1)
#define W1TOT (NE1*HHID*CC)

#define LDB   272          // smem row stride in bytes (136 bf16: 128 + 8 pad)
#define TILEB (128*LDB)    // 34816 B per bf16 tile

// ---- shared memory layout (bytes) ----
#define SM_TK    0
#define SM_TW    512
#define SM_BIAS  1024
#define SM_AHI   2048
#define SM_ALO   (SM_AHI+TILEB)
#define SM_WHI   (SM_ALO+TILEB)
#define SM_WLO   (SM_WHI+TILEB)
#define SM_HHI   (SM_WLO+TILEB)
#define SM_HLO   (SM_HHI+TILEB)
#define SM_TOTAL (SM_HLO+TILEB)   // 210944 B

// ---- device scratch ----
__device__ __nv_bfloat16 g_xhi[(size_t)NTOK*CC];
__device__ __nv_bfloat16 g_xlo[(size_t)NTOK*CC];
__device__ __nv_bfloat16 g_w1hi[W1TOT], g_w1lo[W1TOT];
__device__ __nv_bfloat16 g_w2hi[W1TOT], g_w2lo[W1TOT];
__device__ int   g_tok[EE*NTOK];
__device__ float g_wt[EE*NTOK];
__device__ int   g_cnt[EE];
__device__ float g_probsum[EE];
__device__ int   g_loadsum[EE];

__device__ __forceinline__ float gelu_exact(float v) {
    return 0.5f * v * (1.0f + erff(v * 0.70710678118654752440f));
}

__device__ __forceinline__ void mma16816(float* d, const uint32_t* a, const uint32_t* b) {
    asm volatile("mma.sync.aligned.m16n8k16.row.col.f32.bf16.bf16.f32 "
        "{%0,%1,%2,%3}, {%4,%5,%6,%7}, {%8,%9}, {%0,%1,%2,%3};"
        : "+f"(d[0]), "+f"(d[1]), "+f"(d[2]), "+f"(d[3])
        : "r"(a[0]), "r"(a[1]), "r"(a[2]), "r"(a[3]), "r"(b[0]), "r"(b[1]));
}

// ================================================================ init
__global__ void init_kernel(const float* __restrict__ x, float* __restrict__ out) {
    int i = blockIdx.x * blockDim.x + threadIdx.x;
    ((float4*)out)[i] = ((const float4*)x)[i];
    if (blockIdx.x == 0 && threadIdx.x < EE) {
        g_cnt[threadIdx.x] = 0; g_probsum[threadIdx.x] = 0.f; g_loadsum[threadIdx.x] = 0;
    }
}

// ================================================================ transpose + bf16 split
__global__ void transpose_kernel(const float* __restrict__ x) {
    __shared__ float t[32][33];
    int b = blockIdx.z, c0 = blockIdx.y * 32, s0 = blockIdx.x * 32;
    int tx = threadIdx.x, ty = threadIdx.y;
    #pragma unroll
    for (int i = 0; i < 4; i++) {
        int c = c0 + ty + i * 8;
        t[ty + i * 8][tx] = x[(size_t)(b * CC + c) * HHW + s0 + tx];
    }
    __syncthreads();
    #pragma unroll
    for (int i = 0; i < 4; i++) {
        int s = s0 + ty + i * 8;
        float v = t[tx][ty + i * 8];
        __nv_bfloat16 h = __float2bfloat16(v);
        size_t idx = (size_t)(b * HHW + s) * CC + c0 + tx;
        g_xhi[idx] = h;
        g_xlo[idx] = __float2bfloat16(v - __bfloat162float(h));
    }
}

// ================================================================ weight bf16 split
__global__ void convert_w_kernel(const float* __restrict__ sw1, const float* __restrict__ ew1,
                                 const float* __restrict__ sw2, const float* __restrict__ ew2) {
    int i = blockIdx.x * 256 + threadIdx.x;   // W1TOT threads exactly
    float v1 = (i < EE * HHID * CC) ? ew1[i] : sw1[i - EE * HHID * CC];
    __nv_bfloat16 h1 = __float2bfloat16(v1);
    g_w1hi[i] = h1; g_w1lo[i] = __float2bfloat16(v1 - __bfloat162float(h1));
    float v2 = (i < EE * CC * HHID) ? ew2[i] : sw2[i - EE * CC * HHID];
    __nv_bfloat16 h2 = __float2bfloat16(v2);
    g_w2hi[i] = h2; g_w2lo[i] = __float2bfloat16(v2 - __bfloat162float(h2));
}

// ================================================================ router
__global__ void router_kernel(const float* __restrict__ x,
                              const float* __restrict__ gw,
                              const float* __restrict__ gb) {
    __shared__ float gws[EE * CC];
    __shared__ int   scnt[EE];
    __shared__ float sprob[EE];
    __shared__ int   sbase[EE];
    int tid = threadIdx.x;
    for (int i = tid; i < EE * CC; i += blockDim.x) gws[i] = gw[i];
    if (tid < EE) { scnt[tid] = 0; sprob[tid] = 0.f; }
    __syncthreads();

    int n = blockIdx.x * 256 + tid;
    int b = n / HHW, s = n - b * HHW;
    const float* xb = x + (size_t)b * CC * HHW + s;

    float acc[EE];
    #pragma unroll
    for (int e = 0; e < EE; e++) acc[e] = gb[e];
    for (int c = 0; c < CC; c++) {
        float xv = xb[(size_t)c * HHW];
        #pragma unroll
        for (int e = 0; e < EE; e++) acc[e] += xv * gws[e * CC + c];
    }
    float m = acc[0];
    #pragma unroll
    for (int e = 1; e < EE; e++) m = fmaxf(m, acc[e]);
    float sum = 0.f;
    #pragma unroll
    for (int e = 0; e < EE; e++) { acc[e] = expf(acc[e] - m); sum += acc[e]; }
    float inv = 1.f / sum;
    #pragma unroll
    for (int e = 0; e < EE; e++) { acc[e] *= inv; atomicAdd(&sprob[e], acc[e]); }

    float tmp[EE];
    #pragma unroll
    for (int e = 0; e < EE; e++) tmp[e] = acc[e];
    int id[3]; float pv[3]; float wsum = 0.f;
    #pragma unroll
    for (int k = 0; k < 3; k++) {
        int bi = 0; float bv = tmp[0];
        #pragma unroll
        for (int e = 1; e < EE; e++) if (tmp[e] > bv) { bv = tmp[e]; bi = e; }
        id[k] = bi; pv[k] = bv; tmp[bi] = -1.f; wsum += bv;
    }
    int slot[3];
    #pragma unroll
    for (int k = 0; k < 3; k++) slot[k] = atomicAdd(&scnt[id[k]], 1);
    __syncthreads();
    if (tid < EE) {
        sbase[tid] = atomicAdd(&g_cnt[tid], scnt[tid]);
        atomicAdd(&g_probsum[tid], sprob[tid]);
        atomicAdd(&g_loadsum[tid], scnt[tid]);
    }
    __syncthreads();
    float winv = 1.f / wsum;
    #pragma unroll
    for (int k = 0; k < 3; k++) {
        int pos = sbase[id[k]] + slot[k];
        g_tok[id[k] * NTOK + pos] = n;
        g_wt[id[k] * NTOK + pos]  = pv[k] * winv;
    }
}

// ================================================================ aux loss
__global__ void finalize_kernel(float* __restrict__ out, int out_size) {
    if (threadIdx.x == 0) {
        float a = 0.f;
        for (int e = 0; e < EE; e++) a += g_probsum[e] * (float)g_loadsum[e];
        out[out_size - 1] = (float)EE * a / ((float)NTOK * (float)NTOK);
    }
}

// ================================================================ fused MoE via mma.sync bf16 (hi/lo split)
__global__ __launch_bounds__(256, 1) void moe_mma_kernel(
    const float* __restrict__ sb1, const float* __restrict__ sb2,
    const float* __restrict__ eb1, const float* __restrict__ eb2,
    float* __restrict__ out)
{
    extern __shared__ char sm[];
    int tid = threadIdx.x, wid = tid >> 5, lid = tid & 31;
    int e = blockIdx.y;

    int count = (e < EE) ? g_cnt[e] : NTOK;
    int t0g = blockIdx.x * TMT;
    if (t0g >= count) return;

    const __nv_bfloat16* w1h = g_w1hi + (size_t)e * HHID * CC;
    const __nv_bfloat16* w1l = g_w1lo + (size_t)e * HHID * CC;
    const __nv_bfloat16* w2h = g_w2hi + (size_t)e * CC * HHID;
    const __nv_bfloat16* w2l = g_w2lo + (size_t)e * CC * HHID;
    const float* b1 = (e < EE) ? eb1 + e * HHID : sb1;
    const float* b2 = (e < EE) ? eb2 + e * CC   : sb2;

    int*   tk = (int*)(sm + SM_TK);
    float* tw = (float*)(sm + SM_TW);
    float* bs = (float*)(sm + SM_BIAS);

    if (tid < TMT) {
        int idx = t0g + tid;
        if (e < EE) {
            if (idx < count) { tk[tid] = g_tok[e * NTOK + idx]; tw[tid] = g_wt[e * NTOK + idx]; }
            else             { tk[tid] = 0;                     tw[tid] = 0.f; }
        } else { tk[tid] = idx; tw[tid] = 1.f; }
    }
    __syncthreads();

    // gather pre-split x rows into A tiles (padded row-major [token][k])
    {
        int t = tid >> 1, hf = tid & 1;
        int tok = tk[t];
        const uint4* sh = (const uint4*)(g_xhi + (size_t)tok * CC);
        const uint4* sl = (const uint4*)(g_xlo + (size_t)tok * CC);
        char* dh = sm + SM_AHI + t * LDB;
        char* dl = sm + SM_ALO + t * LDB;
        #pragma unroll
        for (int i = 0; i < 8; i++) {
            int g = hf * 8 + i;
            *(uint4*)(dh + g * 16) = sh[g];
            *(uint4*)(dl + g * 16) = sl[g];
        }
    }

    // warp tiling: 4 (m) x 2 (n); warp tile 32 rows x 64 cols
    int wm = wid & 3, wn = wid >> 2;
    int r_lane = lid >> 2, cb_lane = (lid & 3) * 4;   // byte offset of k-pair (2 bf16 = 4B)

    float acc2[2][8][4];
    #pragma unroll
    for (int mt = 0; mt < 2; mt++)
        #pragma unroll
        for (int nt = 0; nt < 8; nt++)
            #pragma unroll
            for (int q = 0; q < 4; q++) acc2[mt][nt][q] = 0.f;

    for (int j = 0; j < 4; j++) {
        // ---- stage w1 chunk rows [hid_out][k=C] ----
        {
            int n = tid & 127, hf = tid >> 7;
            const uint4* sh = (const uint4*)(w1h + (size_t)(j * 128 + n) * CC);
            const uint4* sl = (const uint4*)(w1l + (size_t)(j * 128 + n) * CC);
            char* dh = sm + SM_WHI + n * LDB;
            char* dl = sm + SM_WLO + n * LDB;
            #pragma unroll
            for (int i = 0; i < 8; i++) {
                int g = hf * 8 + i;
                *(uint4*)(dh + g * 16) = sh[g];
                *(uint4*)(dl + g * 16) = sl[g];
            }
            if (tid < 128) bs[tid] = b1[j * 128 + tid];
        }
        __syncthreads();

        // ---- GEMM1: acc1[tok 32][hid 64] over K=128, 3-pass hi/lo ----
        float acc1[2][8][4];
        #pragma unroll
        for (int mt = 0; mt < 2; mt++)
            #pragma unroll
            for (int nt = 0; nt < 8; nt++)
                #pragma unroll
                for (int q = 0; q < 4; q++) acc1[mt][nt][q] = 0.f;

        #pragma unroll
        for (int k0 = 0; k0 < 8; k0++) {
            int kb = k0 * 32 + cb_lane;
            uint32_t ah[2][4], al[2][4];
            #pragma unroll
            for (int mt = 0; mt < 2; mt++) {
                int row = wm * 32 + mt * 16 + r_lane;
                const char* ph = sm + SM_AHI + row * LDB + kb;
                const char* pl = sm + SM_ALO + row * LDB + kb;
                ah[mt][0] = *(const uint32_t*)(ph);
                ah[mt][1] = *(const uint32_t*)(ph + 8 * LDB);
                ah[mt][2] = *(const uint32_t*)(ph + 16);
                ah[mt][3] = *(const uint32_t*)(ph + 8 * LDB + 16);
                al[mt][0] = *(const uint32_t*)(pl);
                al[mt][1] = *(const uint32_t*)(pl + 8 * LDB);
                al[mt][2] = *(const uint32_t*)(pl + 16);
                al[mt][3] = *(const uint32_t*)(pl + 8 * LDB + 16);
            }
            #pragma unroll
            for (int nt = 0; nt < 8; nt++) {
                int n = wn * 64 + nt * 8 + r_lane;
                const char* ph = sm + SM_WHI + n * LDB + kb;
                const char* pl = sm + SM_WLO + n * LDB + kb;
                uint32_t bh[2], bl[2];
                bh[0] = *(const uint32_t*)(ph); bh[1] = *(const uint32_t*)(ph + 16);
                bl[0] = *(const uint32_t*)(pl); bl[1] = *(const uint32_t*)(pl + 16);
                #pragma unroll
                for (int mt = 0; mt < 2; mt++) {
                    mma16816(acc1[mt][nt], ah[mt], bh);
                    mma16816(acc1[mt][nt], ah[mt], bl);
                    mma16816(acc1[mt][nt], al[mt], bh);
                }
            }
        }
        __syncthreads();   // GEMM1 reads of W done -> safe to overwrite W

        // ---- epilogue1: bias+gelu -> H tile (hi/lo), and stage w2 chunk ----
        #pragma unroll
        for (int mt = 0; mt < 2; mt++) {
            #pragma unroll
            for (int nt = 0; nt < 8; nt++) {
                int c0 = wn * 64 + nt * 8 + (lid & 3) * 2;
                float bi0 = bs[c0], bi1 = bs[c0 + 1];
                #pragma unroll
                for (int half = 0; half < 2; half++) {
                    int row = wm * 32 + mt * 16 + r_lane + half * 8;
                    float g0 = gelu_exact(acc1[mt][nt][half * 2]     + bi0);
                    float g1 = gelu_exact(acc1[mt][nt][half * 2 + 1] + bi1);
                    __nv_bfloat16 h0 = __float2bfloat16(g0), h1 = __float2bfloat16(g1);
                    uint32_t hp = ((uint32_t)__bfloat16_as_ushort(h1) << 16) | __bfloat16_as_ushort(h0);
                    __nv_bfloat16 l0 = __float2bfloat16(g0 - __bfloat162float(h0));
                    __nv_bfloat16 l1 = __float2bfloat16(g1 - __bfloat162float(h1));
                    uint32_t lp = ((uint32_t)__bfloat16_as_ushort(l1) << 16) | __bfloat16_as_ushort(l0);
                    *(uint32_t*)(sm + SM_HHI + row * LDB + c0 * 2) = hp;
                    *(uint32_t*)(sm + SM_HLO + row * LDB + c0 * 2) = lp;
                }
            }
        }
        {
            int n = tid & 127, hf = tid >> 7;
            const uint4* sh = (const uint4*)(w2h + (size_t)n * HHID + j * 128);
            const uint4* sl = (const uint4*)(w2l + (size_t)n * HHID + j * 128);
            char* dh = sm + SM_WHI + n * LDB;
            char* dl = sm + SM_WLO + n * LDB;
            #pragma unroll
            for (int i = 0; i < 8; i++) {
                int g = hf * 8 + i;
                *(uint4*)(dh + g * 16) = sh[g];
                *(uint4*)(dl + g * 16) = sl[g];
            }
        }
        __syncthreads();

        // ---- GEMM2: acc2[tok 32][outc 64] += H . W2^T over this 128-k chunk ----
        #pragma unroll
        for (int k0 = 0; k0 < 8; k0++) {
            int kb = k0 * 32 + cb_lane;
            uint32_t ah[2][4], al[2][4];
            #pragma unroll
            for (int mt = 0; mt < 2; mt++) {
                int row = wm * 32 + mt * 16 + r_lane;
                const char* ph = sm + SM_HHI + row * LDB + kb;
                const char* pl = sm + SM_HLO + row * LDB + kb;
                ah[mt][0] = *(const uint32_t*)(ph);
                ah[mt][1] = *(const uint32_t*)(ph + 8 * LDB);
                ah[mt][2] = *(const uint32_t*)(ph + 16);
                ah[mt][3] = *(const uint32_t*)(ph + 8 * LDB + 16);
                al[mt][0] = *(const uint32_t*)(pl);
                al[mt][1] = *(const uint32_t*)(pl + 8 * LDB);
                al[mt][2] = *(const uint32_t*)(pl + 16);
                al[mt][3] = *(const uint32_t*)(pl + 8 * LDB + 16);
            }
            #pragma unroll
            for (int nt = 0; nt < 8; nt++) {
                int n = wn * 64 + nt * 8 + r_lane;
                const char* ph = sm + SM_WHI + n * LDB + kb;
                const char* pl = sm + SM_WLO + n * LDB + kb;
                uint32_t bh[2], bl[2];
                bh[0] = *(const uint32_t*)(ph); bh[1] = *(const uint32_t*)(ph + 16);
                bl[0] = *(const uint32_t*)(pl); bl[1] = *(const uint32_t*)(pl + 16);
                #pragma unroll
                for (int mt = 0; mt < 2; mt++) {
                    mma16816(acc2[mt][nt], ah[mt], bh);
                    mma16816(acc2[mt][nt], ah[mt], bl);
                    mma16816(acc2[mt][nt], al[mt], bh);
                }
            }
        }
        __syncthreads();   // before next chunk overwrites W / H
    }

    // ---- final epilogue: weighted atomic scatter ----
    if (tid < 128) bs[tid] = b2[tid];
    __syncthreads();
    #pragma unroll
    for (int mt = 0; mt < 2; mt++) {
        #pragma unroll
        for (int half = 0; half < 2; half++) {
            int t = wm * 32 + mt * 16 + r_lane + half * 8;
            int tok = tk[t];
            float w = tw[t];
            int bb = tok / HHW, s = tok - bb * HHW;
            float* ob = out + (size_t)(bb * CC) * HHW + s;
            #pragma unroll
            for (int nt = 0; nt < 8; nt++) {
                int c0 = wn * 64 + nt * 8 + (lid & 3) * 2;
                atomicAdd(&ob[(size_t)c0 * HHW],
                          w * (acc2[mt][nt][half * 2]     + bs[c0]));
                atomicAdd(&ob[(size_t)(c0 + 1) * HHW],
                          w * (acc2[mt][nt][half * 2 + 1] + bs[c0 + 1]));
            }
        }
    }
}

// ================================================================
extern "C" void kernel_launch(void* const* d_in, const int* in_sizes, int n_in,
                              void* d_out, int out_size) {
    const float* x   = (const float*)d_in[0];
    const float* sw1 = (const float*)d_in[1];
    const float* sb1 = (const float*)d_in[2];
    const float* sw2 = (const float*)d_in[3];
    const float* sb2 = (const float*)d_in[4];
    const float* gw  = (const float*)d_in[5];
    const float* gb  = (const float*)d_in[6];
    const float* ew1 = (const float*)d_in[7];
    const float* eb1 = (const float*)d_in[8];
    const float* ew2 = (const float*)d_in[9];
    const float* eb2 = (const float*)d_in[10];
    float* out = (float*)d_out;

    cudaFuncSetAttribute(moe_mma_kernel,
                         cudaFuncAttributeMaxDynamicSharedMemorySize, SM_TOTAL);

    init_kernel<<<NOUT / 4 / 256, 256>>>(x, out);
    transpose_kernel<<<dim3(HHW / 32, CC / 32, BB), dim3(32, 8)>>>(x);
    convert_w_kernel<<<W1TOT / 256, 256>>>(sw1, ew1, sw2, ew2);
    router_kernel<<<NTOK / 256, 256>>>(x, gw, gb);
    moe_mma_kernel<<<dim3(NTOK / TMT, EE + 1), 256, SM_TOTAL>>>(sb1, sb2, eb1, eb2, out);
    finalize_kernel<<<1, 32>>>(out, out_size);
}

// round 6
// speedup vs baseline: 2.4485x; 1.2348x over previous
#include <cuda_runtime.h>
#include <cuda_bf16.h>
#include <math.h>
#include <stdint.h>

#define CC    128          // channels
#define HHID  512          // expert hidden dim
#define EE    8            // routed experts
#define BB    8            // batch
#define HHW   9216         // 96*96
#define NTOK  73728        // BB*HHW
#define NOUT  (NTOK*CC)
#define TMT   128          // tokens per tile (GEMM M)
#define NE1   (EE+1)
#define W1TOT (NE1*HHID*CC)

#define LDB   272          // smem row stride in bytes (136 bf16: 128 + 8 pad)
#define TILEB (128*LDB)    // 34816 B per bf16 tile

// ---- shared memory layout (bytes); lo tile always at hi+TILEB ----
#define SM_TK    0
#define SM_TW    512
#define SM_BIAS  1024
#define SM_AHI   2048
#define SM_ALO   (SM_AHI+TILEB)
#define SM_WHI   (SM_ALO+TILEB)
#define SM_WLO   (SM_WHI+TILEB)
#define SM_HHI   (SM_WLO+TILEB)
#define SM_HLO   (SM_HHI+TILEB)
#define SM_TOTAL (SM_HLO+TILEB)   // 210944 B

// ---- device scratch ----
__device__ __nv_bfloat16 g_xhi[(size_t)NTOK*CC];
__device__ __nv_bfloat16 g_xlo[(size_t)NTOK*CC];
__device__ __nv_bfloat16 g_w1hi[W1TOT], g_w1lo[W1TOT];
__device__ __nv_bfloat16 g_w2hi[W1TOT], g_w2lo[W1TOT];
__device__ int   g_tok[EE*NTOK];
__device__ float g_wt[EE*NTOK];
__device__ int   g_cnt[EE];
__device__ float g_probsum[EE];
__device__ int   g_loadsum[EE];

__device__ __forceinline__ float gelu_exact(float v) {
    return 0.5f * v * (1.0f + erff(v * 0.70710678118654752440f));
}

__device__ __forceinline__ uint32_t smem_u32(const void* p) {
    uint32_t a;
    asm("{ .reg .u64 t; cvta.to.shared.u64 t, %1; cvt.u32.u64 %0, t; }" : "=r"(a) : "l"(p));
    return a;
}

#define CP16(s, g)   asm volatile("cp.async.cg.shared.global [%0], [%1], 16;" :: "r"(s), "l"(g) : "memory")
#define CP_COMMIT()  asm volatile("cp.async.commit_group;" ::: "memory")
#define CP_WAIT0()   asm volatile("cp.async.wait_group 0;" ::: "memory")

#define LDM_X4(r0, r1, r2, r3, a) \
    asm volatile("ldmatrix.sync.aligned.m8n8.x4.shared.b16 {%0,%1,%2,%3}, [%4];" \
        : "=r"(r0), "=r"(r1), "=r"(r2), "=r"(r3) : "r"(a))

__device__ __forceinline__ void mma16816(float* d, const uint32_t* a, const uint32_t* b) {
    asm volatile("mma.sync.aligned.m16n8k16.row.col.f32.bf16.bf16.f32 "
        "{%0,%1,%2,%3}, {%4,%5,%6,%7}, {%8,%9}, {%0,%1,%2,%3};"
        : "+f"(d[0]), "+f"(d[1]), "+f"(d[2]), "+f"(d[3])
        : "r"(a[0]), "r"(a[1]), "r"(a[2]), "r"(a[3]), "r"(b[0]), "r"(b[1]));
}

// one 128x128x128 GEMM chunk, 3-pass bf16 hi/lo. aHi/wHi are smem u32 addrs of
// hi tiles (lo at +TILEB). acc[mt][nt][4] accumulates [32 tok][64 cols] per warp.
__device__ __forceinline__ void gemm_chunk(uint32_t aHi, uint32_t wHi,
                                           float acc[2][8][4], int lid, int wm, int wn) {
    // ldmatrix lane address components
    int a_r   = (lid & 7) + ((lid >> 3) & 1) * 8;
    int a_ko  = ((lid >> 4) & 1) * 16;
    int b_n   = (lid & 7) + ((lid >> 4) & 1) * 8;
    int b_ko  = ((lid >> 3) & 1) * 16;
    uint32_t aBase = aHi + (uint32_t)(wm * 32 + a_r) * LDB + a_ko;
    uint32_t bBase = wHi + (uint32_t)(wn * 64 + b_n) * LDB + b_ko;

    #pragma unroll 2
    for (int k0 = 0; k0 < 8; k0++) {
        uint32_t kb = k0 * 32;
        uint32_t ah[2][4], al[2][4];
        #pragma unroll
        for (int mt = 0; mt < 2; mt++) {
            uint32_t ad = aBase + (uint32_t)(mt * 16) * LDB + kb;
            LDM_X4(ah[mt][0], ah[mt][1], ah[mt][2], ah[mt][3], ad);
            LDM_X4(al[mt][0], al[mt][1], al[mt][2], al[mt][3], ad + TILEB);
        }
        #pragma unroll
        for (int ntp = 0; ntp < 4; ntp++) {
            uint32_t bd = bBase + (uint32_t)(ntp * 16) * LDB + kb;
            uint32_t bh[4], bl[4];
            LDM_X4(bh[0], bh[1], bh[2], bh[3], bd);
            LDM_X4(bl[0], bl[1], bl[2], bl[3], bd + TILEB);
            #pragma unroll
            for (int g = 0; g < 2; g++) {
                int nt = ntp * 2 + g;
                #pragma unroll
                for (int mt = 0; mt < 2; mt++) {
                    mma16816(acc[mt][nt], ah[mt], bh + 2 * g);
                    mma16816(acc[mt][nt], ah[mt], bl + 2 * g);
                    mma16816(acc[mt][nt], al[mt], bh + 2 * g);
                }
            }
        }
    }
}

// ================================================================ init
__global__ void init_kernel(const float* __restrict__ x, float* __restrict__ out) {
    int i = blockIdx.x * blockDim.x + threadIdx.x;
    ((float4*)out)[i] = ((const float4*)x)[i];
    if (blockIdx.x == 0 && threadIdx.x < EE) {
        g_cnt[threadIdx.x] = 0; g_probsum[threadIdx.x] = 0.f; g_loadsum[threadIdx.x] = 0;
    }
}

// ================================================================ transpose + bf16 split
__global__ void transpose_kernel(const float* __restrict__ x) {
    __shared__ float t[32][33];
    int b = blockIdx.z, c0 = blockIdx.y * 32, s0 = blockIdx.x * 32;
    int tx = threadIdx.x, ty = threadIdx.y;
    #pragma unroll
    for (int i = 0; i < 4; i++) {
        int c = c0 + ty + i * 8;
        t[ty + i * 8][tx] = x[(size_t)(b * CC + c) * HHW + s0 + tx];
    }
    __syncthreads();
    #pragma unroll
    for (int i = 0; i < 4; i++) {
        int s = s0 + ty + i * 8;
        float v = t[tx][ty + i * 8];
        __nv_bfloat16 h = __float2bfloat16(v);
        size_t idx = (size_t)(b * HHW + s) * CC + c0 + tx;
        g_xhi[idx] = h;
        g_xlo[idx] = __float2bfloat16(v - __bfloat162float(h));
    }
}

// ================================================================ weight bf16 split
__global__ void convert_w_kernel(const float* __restrict__ sw1, const float* __restrict__ ew1,
                                 const float* __restrict__ sw2, const float* __restrict__ ew2) {
    int i = blockIdx.x * 256 + threadIdx.x;
    float v1 = (i < EE * HHID * CC) ? ew1[i] : sw1[i - EE * HHID * CC];
    __nv_bfloat16 h1 = __float2bfloat16(v1);
    g_w1hi[i] = h1; g_w1lo[i] = __float2bfloat16(v1 - __bfloat162float(h1));
    float v2 = (i < EE * CC * HHID) ? ew2[i] : sw2[i - EE * CC * HHID];
    __nv_bfloat16 h2 = __float2bfloat16(v2);
    g_w2hi[i] = h2; g_w2lo[i] = __float2bfloat16(v2 - __bfloat162float(h2));
}

// ================================================================ router
__global__ void router_kernel(const float* __restrict__ x,
                              const float* __restrict__ gw,
                              const float* __restrict__ gb) {
    __shared__ float gws[EE * CC];
    __shared__ int   scnt[EE];
    __shared__ float sprob[EE];
    __shared__ int   sbase[EE];
    int tid = threadIdx.x;
    for (int i = tid; i < EE * CC; i += blockDim.x) gws[i] = gw[i];
    if (tid < EE) { scnt[tid] = 0; sprob[tid] = 0.f; }
    __syncthreads();

    int n = blockIdx.x * 256 + tid;
    int b = n / HHW, s = n - b * HHW;
    const float* xb = x + (size_t)b * CC * HHW + s;

    float acc[EE];
    #pragma unroll
    for (int e = 0; e < EE; e++) acc[e] = gb[e];
    #pragma unroll 8
    for (int c = 0; c < CC; c++) {
        float xv = __ldg(&xb[(size_t)c * HHW]);
        #pragma unroll
        for (int e = 0; e < EE; e++) acc[e] += xv * gws[e * CC + c];
    }
    float m = acc[0];
    #pragma unroll
    for (int e = 1; e < EE; e++) m = fmaxf(m, acc[e]);
    float sum = 0.f;
    #pragma unroll
    for (int e = 0; e < EE; e++) { acc[e] = expf(acc[e] - m); sum += acc[e]; }
    float inv = 1.f / sum;
    #pragma unroll
    for (int e = 0; e < EE; e++) { acc[e] *= inv; atomicAdd(&sprob[e], acc[e]); }

    float tmp[EE];
    #pragma unroll
    for (int e = 0; e < EE; e++) tmp[e] = acc[e];
    int id[3]; float pv[3]; float wsum = 0.f;
    #pragma unroll
    for (int k = 0; k < 3; k++) {
        int bi = 0; float bv = tmp[0];
        #pragma unroll
        for (int e = 1; e < EE; e++) if (tmp[e] > bv) { bv = tmp[e]; bi = e; }
        id[k] = bi; pv[k] = bv; tmp[bi] = -1.f; wsum += bv;
    }
    int slot[3];
    #pragma unroll
    for (int k = 0; k < 3; k++) slot[k] = atomicAdd(&scnt[id[k]], 1);
    __syncthreads();
    if (tid < EE) {
        sbase[tid] = atomicAdd(&g_cnt[tid], scnt[tid]);
        atomicAdd(&g_probsum[tid], sprob[tid]);
        atomicAdd(&g_loadsum[tid], scnt[tid]);
    }
    __syncthreads();
    float winv = 1.f / wsum;
    #pragma unroll
    for (int k = 0; k < 3; k++) {
        int pos = sbase[id[k]] + slot[k];
        g_tok[id[k] * NTOK + pos] = n;
        g_wt[id[k] * NTOK + pos]  = pv[k] * winv;
    }
}

// ================================================================ aux loss
__global__ void finalize_kernel(float* __restrict__ out, int out_size) {
    if (threadIdx.x == 0) {
        float a = 0.f;
        for (int e = 0; e < EE; e++) a += g_probsum[e] * (float)g_loadsum[e];
        out[out_size - 1] = (float)EE * a / ((float)NTOK * (float)NTOK);
    }
}

// ================================================================ fused MoE (HMMA + ldmatrix + cp.async)
__global__ __launch_bounds__(256, 1) void moe_mma_kernel(
    const float* __restrict__ sb1, const float* __restrict__ sb2,
    const float* __restrict__ eb1, const float* __restrict__ eb2,
    float* __restrict__ out)
{
    extern __shared__ char sm[];
    uint32_t smb = smem_u32(sm);
    int tid = threadIdx.x, wid = tid >> 5, lid = tid & 31;
    int e = blockIdx.y;

    int count = (e < EE) ? g_cnt[e] : NTOK;
    int t0g = blockIdx.x * TMT;
    if (t0g >= count) return;

    const __nv_bfloat16* w1h = g_w1hi + (size_t)e * HHID * CC;
    const __nv_bfloat16* w1l = g_w1lo + (size_t)e * HHID * CC;
    const __nv_bfloat16* w2h = g_w2hi + (size_t)e * CC * HHID;
    const __nv_bfloat16* w2l = g_w2lo + (size_t)e * CC * HHID;
    const float* b1 = (e < EE) ? eb1 + e * HHID : sb1;
    const float* b2 = (e < EE) ? eb2 + e * CC   : sb2;

    int*   tk = (int*)(sm + SM_TK);
    float* tw = (float*)(sm + SM_TW);
    float* bs = (float*)(sm + SM_BIAS);

    if (tid < TMT) {
        int idx = t0g + tid;
        if (e < EE) {
            if (idx < count) { tk[tid] = g_tok[e * NTOK + idx]; tw[tid] = g_wt[e * NTOK + idx]; }
            else             { tk[tid] = 0;                     tw[tid] = 0.f; }
        } else { tk[tid] = idx; tw[tid] = 1.f; }
    }
    __syncthreads();

    // gather pre-split x rows into A tiles via cp.async
    {
        int t = tid >> 1, hf = tid & 1;
        int tok = tk[t];
        const char* sh = (const char*)(g_xhi + (size_t)tok * CC) + hf * 128;
        const char* sl = (const char*)(g_xlo + (size_t)tok * CC) + hf * 128;
        uint32_t dh = smb + SM_AHI + t * LDB + hf * 128;
        #pragma unroll
        for (int i = 0; i < 8; i++) {
            CP16(dh + i * 16,         sh + i * 16);
            CP16(dh + TILEB + i * 16, sl + i * 16);
        }
    }

    int wm = wid & 3, wn = wid >> 2;
    int r_lane = lid >> 2;
    int stg_n = tid & 127, stg_h = tid >> 7;   // staging: row, 128B half

    float acc2[2][8][4];
    #pragma unroll
    for (int mt = 0; mt < 2; mt++)
        #pragma unroll
        for (int nt = 0; nt < 8; nt++)
            #pragma unroll
            for (int q = 0; q < 4; q++) acc2[mt][nt][q] = 0.f;

    for (int j = 0; j < 4; j++) {
        // ---- stage w1 chunk rows [hid_out][k=C] ----
        {
            const char* sh = (const char*)(w1h + (size_t)(j * 128 + stg_n) * CC) + stg_h * 128;
            const char* sl = (const char*)(w1l + (size_t)(j * 128 + stg_n) * CC) + stg_h * 128;
            uint32_t dh = smb + SM_WHI + stg_n * LDB + stg_h * 128;
            #pragma unroll
            for (int i = 0; i < 8; i++) {
                CP16(dh + i * 16,         sh + i * 16);
                CP16(dh + TILEB + i * 16, sl + i * 16);
            }
            if (tid < 128) bs[tid] = b1[j * 128 + tid];
        }
        CP_COMMIT(); CP_WAIT0();
        __syncthreads();

        // ---- GEMM1 ----
        float acc1[2][8][4];
        #pragma unroll
        for (int mt = 0; mt < 2; mt++)
            #pragma unroll
            for (int nt = 0; nt < 8; nt++)
                #pragma unroll
                for (int q = 0; q < 4; q++) acc1[mt][nt][q] = 0.f;
        gemm_chunk(smb + SM_AHI, smb + SM_WHI, acc1, lid, wm, wn);
        __syncthreads();   // GEMM1 reads done -> safe to overwrite W

        // ---- epilogue1: bias+gelu -> H tile (hi/lo); stage w2 chunk ----
        {
            const char* sh = (const char*)(w2h + (size_t)stg_n * HHID + j * 128) + stg_h * 128;
            const char* sl = (const char*)(w2l + (size_t)stg_n * HHID + j * 128) + stg_h * 128;
            uint32_t dh = smb + SM_WHI + stg_n * LDB + stg_h * 128;
            #pragma unroll
            for (int i = 0; i < 8; i++) {
                CP16(dh + i * 16,         sh + i * 16);
                CP16(dh + TILEB + i * 16, sl + i * 16);
            }
        }
        CP_COMMIT();
        #pragma unroll
        for (int mt = 0; mt < 2; mt++) {
            #pragma unroll
            for (int nt = 0; nt < 8; nt++) {
                int c0 = wn * 64 + nt * 8 + (lid & 3) * 2;
                float bi0 = bs[c0], bi1 = bs[c0 + 1];
                #pragma unroll
                for (int half = 0; half < 2; half++) {
                    int row = wm * 32 + mt * 16 + r_lane + half * 8;
                    float g0 = gelu_exact(acc1[mt][nt][half * 2]     + bi0);
                    float g1 = gelu_exact(acc1[mt][nt][half * 2 + 1] + bi1);
                    __nv_bfloat16 h0 = __float2bfloat16(g0), h1 = __float2bfloat16(g1);
                    uint32_t hp = ((uint32_t)__bfloat16_as_ushort(h1) << 16) | __bfloat16_as_ushort(h0);
                    __nv_bfloat16 l0 = __float2bfloat16(g0 - __bfloat162float(h0));
                    __nv_bfloat16 l1 = __float2bfloat16(g1 - __bfloat162float(h1));
                    uint32_t lp = ((uint32_t)__bfloat16_as_ushort(l1) << 16) | __bfloat16_as_ushort(l0);
                    *(uint32_t*)(sm + SM_HHI + row * LDB + c0 * 2) = hp;
                    *(uint32_t*)(sm + SM_HLO + row * LDB + c0 * 2) = lp;
                }
            }
        }
        CP_WAIT0();
        __syncthreads();

        // ---- GEMM2 (accumulate across chunks) ----
        gemm_chunk(smb + SM_HHI, smb + SM_WHI, acc2, lid, wm, wn);
        __syncthreads();   // before next chunk overwrites W / H
    }

    // ---- final epilogue: weighted atomic scatter ----
    if (tid < 128) bs[tid] = b2[tid];
    __syncthreads();
    #pragma unroll
    for (int mt = 0; mt < 2; mt++) {
        #pragma unroll
        for (int half = 0; half < 2; half++) {
            int t = wm * 32 + mt * 16 + r_lane + half * 8;
            int tok = tk[t];
            float w = tw[t];
            int bb = tok / HHW, s = tok - bb * HHW;
            float* ob = out + (size_t)(bb * CC) * HHW + s;
            #pragma unroll
            for (int nt = 0; nt < 8; nt++) {
                int c0 = wn * 64 + nt * 8 + (lid & 3) * 2;
                atomicAdd(&ob[(size_t)c0 * HHW],
                          w * (acc2[mt][nt][half * 2]     + bs[c0]));
                atomicAdd(&ob[(size_t)(c0 + 1) * HHW],
                          w * (acc2[mt][nt][half * 2 + 1] + bs[c0 + 1]));
            }
        }
    }
}

// ================================================================
extern "C" void kernel_launch(void* const* d_in, const int* in_sizes, int n_in,
                              void* d_out, int out_size) {
    const float* x   = (const float*)d_in[0];
    const float* sw1 = (const float*)d_in[1];
    const float* sb1 = (const float*)d_in[2];
    const float* sw2 = (const float*)d_in[3];
    const float* sb2 = (const float*)d_in[4];
    const float* gw  = (const float*)d_in[5];
    const float* gb  = (const float*)d_in[6];
    const float* ew1 = (const float*)d_in[7];
    const float* eb1 = (const float*)d_in[8];
    const float* ew2 = (const float*)d_in[9];
    const float* eb2 = (const float*)d_in[10];
    float* out = (float*)d_out;

    cudaFuncSetAttribute(moe_mma_kernel,
                         cudaFuncAttributeMaxDynamicSharedMemorySize, SM_TOTAL);

    init_kernel<<<NOUT / 4 / 256, 256>>>(x, out);
    transpose_kernel<<<dim3(HHW / 32, CC / 32, BB), dim3(32, 8)>>>(x);
    convert_w_kernel<<<W1TOT / 256, 256>>>(sw1, ew1, sw2, ew2);
    router_kernel<<<NTOK / 256, 256>>>(x, gw, gb);
    moe_mma_kernel<<<dim3(NTOK / TMT, EE + 1), 256, SM_TOTAL>>>(sb1, sb2, eb1, eb2, out);
    finalize_kernel<<<1, 32>>>(out, out_size);
}